// round 12
// baseline (speedup 1.0000x reference)
#include <cuda_runtime.h>
#include <cuda_bf16.h>
#include <math.h>
#include <stdint.h>
#include <string.h>

// Problem dims (fixed per reference)
#define T_DIM 256
#define B_DIM 256
#define V_DIM 512
#define H_DIM 1024
#define M_ALL (T_DIM * B_DIM)          // 65536
#define BH    (B_DIM * H_DIM)          // 262144
#define TBV   (T_DIM * B_DIM * V_DIM)  // 33554432

#define KSPLIT 4
#define NBLK   128                      // 8 n-tiles x 4 b-tiles x 4 k-splits

// Scratch (allocation-free rule)
__device__ float g_xh[(size_t)M_ALL * H_DIM];        // 256 MB
__device__ float g_hs[(size_t)M_ALL * H_DIM];        // 256 MB
__device__ float g_part[2 * KSPLIT * (size_t)BH];    // 8 MB double-buffered partials
__device__ unsigned g_bar;                           // global barrier counter
__device__ unsigned g_pad_sink;                      // pad kernel target

// ---------------------------------------------------------------------------
// packed f32x2 helpers (for the SGEMM kernels)
// ---------------------------------------------------------------------------
__device__ __forceinline__ unsigned long long dup2(float v) {
    unsigned long long r;
    asm("mov.b64 %0,{%1,%1};" : "=l"(r) : "f"(v));
    return r;
}
__device__ __forceinline__ void fma2(unsigned long long& d,
                                     unsigned long long a,
                                     unsigned long long b) {
    asm("fma.rn.f32x2 %0,%1,%2,%0;" : "+l"(d) : "l"(a), "l"(b));
}
__device__ __forceinline__ float2 unpk(unsigned long long v) {
    float2 f;
    asm("mov.b64 {%0,%1},%2;" : "=f"(f.x), "=f"(f.y) : "l"(v));
    return f;
}

// ---------------------------------------------------------------------------
// bf16 / mma helpers (sm_80+ baseline PTX; safe for compute_103)
// ---------------------------------------------------------------------------
__device__ __forceinline__ uint32_t pack_bf16x2(float a, float b) {
    __nv_bfloat162 p = __floats2bfloat162_rn(a, b);
    uint32_t u;
    memcpy(&u, &p, 4);
    return u;
}

__device__ __forceinline__ void mma_bf16(float* c, const uint32_t* a,
                                         const uint32_t* b) {
    asm volatile(
        "mma.sync.aligned.m16n8k16.row.col.f32.bf16.bf16.f32 "
        "{%0,%1,%2,%3}, {%4,%5,%6,%7}, {%8,%9}, {%0,%1,%2,%3};"
        : "+f"(c[0]), "+f"(c[1]), "+f"(c[2]), "+f"(c[3])
        : "r"(a[0]), "r"(a[1]), "r"(a[2]), "r"(a[3]), "r"(b[0]), "r"(b[1]));
}

__device__ __forceinline__ void ldsm_x4(uint32_t* r, uint32_t addr) {
    asm volatile(
        "ldmatrix.sync.aligned.m8n8.x4.shared.b16 {%0,%1,%2,%3}, [%4];"
        : "=r"(r[0]), "=r"(r[1]), "=r"(r[2]), "=r"(r[3]) : "r"(addr));
}

__device__ __forceinline__ uint32_t smem_to_u32(const void* p) {
    uint32_t a;
    asm("{ .reg .u64 t; cvta.to.shared.u64 t, %1; cvt.u32.u64 %0, t; }"
        : "=r"(a) : "l"(p));
    return a;
}

// Release/acquire device-wide barrier (no full MEMBAR.GPU flush).
// One arrival per block; tid 0 spins with acquire loads.
__device__ __forceinline__ void grid_barrier(unsigned target)
{
    __syncthreads();
    if (threadIdx.x == 0) {
        asm volatile("red.release.gpu.add.u32 [%0], 1;"
                     :: "l"(&g_bar) : "memory");
        unsigned v;
        while (true) {
            asm volatile("ld.acquire.gpu.u32 %0, [%1];"
                         : "=r"(v) : "l"(&g_bar) : "memory");
            if (v >= target) break;
            __nanosleep(64);
        }
    }
    __syncthreads();
}

// ---------------------------------------------------------------------------
// fp32 SGEMM with f32x2 inner loop: C[M,N] = A[M,K] @ B[K,N] + bias[N]
// ---------------------------------------------------------------------------
__global__ void __launch_bounds__(256)
sgemm_bias_kernel(const float* __restrict__ A, const float* __restrict__ B,
                  const float* __restrict__ bias, float* __restrict__ C,
                  int M, int N, int K)
{
    constexpr int BM = 128, BN = 128, BK = 8, TM = 8, TN = 8;
    __shared__ __align__(16) float As[BK][BM];
    __shared__ __align__(16) float Bs[BK][BN];

    const int tid = threadIdx.x;
    const int bm = blockIdx.y * BM;
    const int bn = blockIdx.x * BN;

    const int tx = tid % (BN / TN);
    const int ty = tid / (BN / TN);
    const int row0 = ty * TM;
    const int col0 = tx * TN;

    const int aRow  = tid / (BK / 4);
    const int aCol4 = (tid % (BK / 4)) * 4;
    const int bRow  = tid / (BN / 4);
    const int bCol4 = (tid % (BN / 4)) * 4;

    const float* Aptr = A + (size_t)bm * K;
    const float* Bptr = B + bn;

    unsigned long long acc[TM][TN / 2];
#pragma unroll
    for (int i = 0; i < TM; i++)
#pragma unroll
        for (int j = 0; j < TN / 2; j++) acc[i][j] = 0ull;

    for (int k0 = 0; k0 < K; k0 += BK) {
        float4 a4 = *(const float4*)(Aptr + (size_t)aRow * K + k0 + aCol4);
        As[aCol4 + 0][aRow] = a4.x;
        As[aCol4 + 1][aRow] = a4.y;
        As[aCol4 + 2][aRow] = a4.z;
        As[aCol4 + 3][aRow] = a4.w;
        *(float4*)&Bs[bRow][bCol4] =
            *(const float4*)(Bptr + (size_t)(k0 + bRow) * N + bCol4);
        __syncthreads();

#pragma unroll
        for (int k = 0; k < BK; k++) {
            unsigned long long ra[TM];
#pragma unroll
            for (int i = 0; i < TM; i++) ra[i] = dup2(As[k][row0 + i]);
            const ulonglong2* bp = (const ulonglong2*)&Bs[k][col0];
            ulonglong2 rb0 = bp[0];
            ulonglong2 rb1 = bp[1];
#pragma unroll
            for (int i = 0; i < TM; i++) {
                fma2(acc[i][0], ra[i], rb0.x);
                fma2(acc[i][1], ra[i], rb0.y);
                fma2(acc[i][2], ra[i], rb1.x);
                fma2(acc[i][3], ra[i], rb1.y);
            }
        }
        __syncthreads();
    }

    float4 bv0 = *(const float4*)(bias + bn + col0);
    float4 bv1 = *(const float4*)(bias + bn + col0 + 4);
#pragma unroll
    for (int i = 0; i < TM; i++) {
        const size_t gr = (size_t)(bm + row0 + i);
        float2 a0 = unpk(acc[i][0]);
        float2 a1 = unpk(acc[i][1]);
        float2 a2 = unpk(acc[i][2]);
        float2 a3 = unpk(acc[i][3]);
        float4 v0 = make_float4(a0.x + bv0.x, a0.y + bv0.y,
                                a1.x + bv0.z, a1.y + bv0.w);
        float4 v1 = make_float4(a2.x + bv1.x, a2.y + bv1.y,
                                a3.x + bv1.z, a3.y + bv1.w);
        *(float4*)(C + gr * N + bn + col0)     = v0;
        *(float4*)(C + gr * N + bn + col0 + 4) = v1;
    }
}

// ---------------------------------------------------------------------------
// Persistent HMMA recurrence — ONE device barrier per step.
// 128 blocks = 8 nt x 4 bt x 4 ks. Block tile: 64 b x 128 n over k 256.
// Smem: Whi/Wlo [128 n][256 k] bf16 (split once, ~132 KB), Hhi/Hlo [64 b][256 k].
// Step tt: stage h_{tt-1} (tt==1: from hs[0]; else FUSED: tanh(xh + sum of 4
// partials) computed during staging; nt==0 blocks also write hs[tt-1] fp32);
// sync; compute partials_tt (16 warps, warp tile 16b x 32n, ldmatrix + 3-pass
// bf16-split mma); STG partials to buffer tt&1; release/acquire grid barrier.
// Epilogue: nt==0 blocks write h_{T-1} fp32.
// ---------------------------------------------------------------------------
#define WST     132                       // words per smem row (264 B)
#define W_TILE  (128 * WST)               // words per W tile
#define H_TILE  (64 * WST)                // words per H tile
#define PS_SMEM ((2 * W_TILE + 2 * H_TILE) * 4)   // ~198 KB

__global__ void __launch_bounds__(512, 1)
rnn_persistent_mma(const float* __restrict__ W,
                   const float* __restrict__ xh,
                   float* __restrict__ hs)
{
    extern __shared__ __align__(16) uint32_t smw[];
    uint32_t* Whi = smw;
    uint32_t* Wlo = smw + W_TILE;
    uint32_t* Hhi = smw + 2 * W_TILE;
    uint32_t* Hlo = smw + 2 * W_TILE + H_TILE;

    const uint32_t sWhi = smem_to_u32(Whi);
    const uint32_t sHhi = sWhi + 2 * W_TILE * 4;

    const int tid  = threadIdx.x;
    const int wid  = tid >> 5;
    const int lane = tid & 31;
    const int bx   = blockIdx.x;
    const int ks   = bx & 3;          // k-split 0..3 (k 256)
    const int bt   = (bx >> 2) & 3;   // b-tile  0..3 (b 64)
    const int nt   = bx >> 4;         // n-tile  0..7 (n 128)
    const int k0   = ks * 256;
    const int b0   = bt * 64;
    const int n0   = nt * 128;

    // fragment lane decomposition (epilogue stores)
    const int g = lane >> 2;          // 0..7
    const int t = lane & 3;           // 0..3

    // warp tile: wm 0..3 (16 b-rows), wn 0..3 (32 n-cols)
    const int wm = wid & 3;
    const int wn = wid >> 2;

    // ---- ldmatrix lane-address bases (advance 32 B per k16-step) ----
    uint32_t aHiA, aLoA;
    {
        const int row = wm * 16 + (lane & 15);
        const uint32_t w = (uint32_t)row * WST + ((lane >> 4) << 2);
        aHiA = sHhi + w * 4;
        aLoA = aHiA + H_TILE * 4;
    }
    uint32_t bHiA[2], bLoA[2];
#pragma unroll
    for (int p = 0; p < 2; p++) {
        const int row = wn * 32 + p * 16 + ((lane >> 4) << 3) + (lane & 7);
        const uint32_t w = (uint32_t)row * WST + (((lane >> 3) & 1) << 2);
        bHiA[p] = sWhi + w * 4;
        bLoA[p] = bHiA[p] + W_TILE * 4;
    }

    // ---- one-time: split W slice into bf16 hi/lo, layout [n][k] ----
    for (int idx = tid; idx < 128 * 128; idx += 512) {
        const int n = idx & 127;
        const int c = idx >> 7;                 // k-pair 0..127
        const float w0 = W[(size_t)(k0 + 2 * c)     * H_DIM + n0 + n];
        const float w1 = W[(size_t)(k0 + 2 * c + 1) * H_DIM + n0 + n];
        const float h0 = __bfloat162float(__float2bfloat16(w0));
        const float h1 = __bfloat162float(__float2bfloat16(w1));
        Whi[n * WST + c] = pack_bf16x2(w0, w1);
        Wlo[n * WST + c] = pack_bf16x2(w0 - h0, w1 - h1);
    }

    // staging thread mapping: row srow (0..63), k-group kg (8 float4 slots)
    const int srow = tid >> 3;          // 0..63
    const int kg   = (tid & 7) * 32;    // k offset 0..224
    const size_t eoff = (size_t)(b0 + srow) * H_DIM + k0 + kg;

    __syncthreads();

    for (int tt = 1; tt < T_DIM; tt++) {
        // ---- stage h_{tt-1} as bf16 hi/lo [b][k] (fused reduce+tanh) ----
        {
            uint32_t* dh = Hhi + srow * WST + (kg >> 1);
            uint32_t* dl = Hlo + srow * WST + (kg >> 1);
            if (tt == 1) {
#pragma unroll
                for (int i = 0; i < 8; i++) {
                    float4 s = *(const float4*)(hs + eoff + 4 * i);
                    const float hx = __bfloat162float(__float2bfloat16(s.x));
                    const float hy = __bfloat162float(__float2bfloat16(s.y));
                    const float hz = __bfloat162float(__float2bfloat16(s.z));
                    const float hw = __bfloat162float(__float2bfloat16(s.w));
                    *(uint2*)(dh + 2 * i) = make_uint2(pack_bf16x2(s.x, s.y),
                                                       pack_bf16x2(s.z, s.w));
                    *(uint2*)(dl + 2 * i) =
                        make_uint2(pack_bf16x2(s.x - hx, s.y - hy),
                                   pack_bf16x2(s.z - hz, s.w - hw));
                }
            } else {
                const float* pb = g_part + (size_t)(((tt - 1) & 1) * KSPLIT) * BH;
                const float* xr = xh + (size_t)(tt - 1) * BH;
                float* ho = hs + (size_t)(tt - 1) * BH;
#pragma unroll
                for (int i = 0; i < 8; i++) {
                    const size_t o = eoff + 4 * i;
                    float4 s = *(const float4*)(xr + o);
#pragma unroll
                    for (int sp = 0; sp < KSPLIT; sp++) {
                        float4 p = *(const float4*)(pb + (size_t)sp * BH + o);
                        s.x += p.x; s.y += p.y; s.z += p.z; s.w += p.w;
                    }
                    s.x = tanhf(s.x);
                    s.y = tanhf(s.y);
                    s.z = tanhf(s.z);
                    s.w = tanhf(s.w);
                    if (nt == 0) *(float4*)(ho + o) = s;   // hs fp32 for GEMM3
                    const float hx = __bfloat162float(__float2bfloat16(s.x));
                    const float hy = __bfloat162float(__float2bfloat16(s.y));
                    const float hz = __bfloat162float(__float2bfloat16(s.z));
                    const float hw = __bfloat162float(__float2bfloat16(s.w));
                    *(uint2*)(dh + 2 * i) = make_uint2(pack_bf16x2(s.x, s.y),
                                                       pack_bf16x2(s.z, s.w));
                    *(uint2*)(dl + 2 * i) =
                        make_uint2(pack_bf16x2(s.x - hx, s.y - hy),
                                   pack_bf16x2(s.z - hz, s.w - hw));
                }
            }
        }
        __syncthreads();

        // ---- compute warp tile 16b x 32n over k 256, 3-product split ----
        float acc[4][4];
#pragma unroll
        for (int nn = 0; nn < 4; nn++)
#pragma unroll
            for (int j = 0; j < 4; j++) acc[nn][j] = 0.0f;

#pragma unroll 4
        for (int kst = 0; kst < 16; kst++) {
            const uint32_t kb = (uint32_t)kst * 32;
            uint32_t ah[4], al[4], bh0[4], bh1[4], bl0[4], bl1[4];
            ldsm_x4(ah, aHiA + kb);
            ldsm_x4(bh0, bHiA[0] + kb);
            ldsm_x4(bh1, bHiA[1] + kb);
            ldsm_x4(al, aLoA + kb);
            ldsm_x4(bl0, bLoA[0] + kb);
            ldsm_x4(bl1, bLoA[1] + kb);

            mma_bf16(acc[0], ah, bh0);
            mma_bf16(acc[1], ah, bh0 + 2);
            mma_bf16(acc[2], ah, bh1);
            mma_bf16(acc[3], ah, bh1 + 2);

            mma_bf16(acc[0], ah, bl0);
            mma_bf16(acc[1], ah, bl0 + 2);
            mma_bf16(acc[2], ah, bl1);
            mma_bf16(acc[3], ah, bl1 + 2);

            mma_bf16(acc[0], al, bh0);
            mma_bf16(acc[1], al, bh0 + 2);
            mma_bf16(acc[2], al, bh1);
            mma_bf16(acc[3], al, bh1 + 2);
        }

        // ---- write fp32 partial tile (buffer tt&1) ----
        {
            float* part = g_part + (size_t)((tt & 1) * KSPLIT + ks) * BH;
            const int row0 = b0 + wm * 16 + g;
#pragma unroll
            for (int nn = 0; nn < 4; nn++) {
                const int col = n0 + wn * 32 + nn * 8 + 2 * t;
                *(float2*)(part + (size_t)row0 * H_DIM + col) =
                    make_float2(acc[nn][0], acc[nn][1]);
                *(float2*)(part + (size_t)(row0 + 8) * H_DIM + col) =
                    make_float2(acc[nn][2], acc[nn][3]);
            }
        }

        // ---- single device barrier per step ----
        grid_barrier((unsigned)tt * NBLK);
    }

    // ---- epilogue: h_{T-1} fp32 (consumed by GEMM3 / state copy) ----
    if (nt == 0) {
        const float* pb = g_part + (size_t)(((T_DIM - 1) & 1) * KSPLIT) * BH;
        const float* xr = xh + (size_t)(T_DIM - 1) * BH;
        float* ho = hs + (size_t)(T_DIM - 1) * BH;
#pragma unroll
        for (int i = 0; i < 8; i++) {
            const size_t o = eoff + 4 * i;
            float4 s = *(const float4*)(xr + o);
#pragma unroll
            for (int sp = 0; sp < KSPLIT; sp++) {
                float4 p = *(const float4*)(pb + (size_t)sp * BH + o);
                s.x += p.x; s.y += p.y; s.z += p.z; s.w += p.w;
            }
            s.x = tanhf(s.x);
            s.y = tanhf(s.y);
            s.z = tanhf(s.z);
            s.w = tanhf(s.w);
            *(float4*)(ho + o) = s;
        }
    }
}

// h_0 = tanh(xh_0); also resets the persistent kernel's barrier counter.
__global__ void __launch_bounds__(256)
init_kernel(const float* __restrict__ x, float* __restrict__ y)
{
    if (blockIdx.x == 0 && threadIdx.x == 0) g_bar = 0u;
    const size_t i = ((size_t)blockIdx.x * blockDim.x + threadIdx.x) * 4;
    float4 v = *(const float4*)(x + i);
    v.x = tanhf(v.x);
    v.y = tanhf(v.y);
    v.z = tanhf(v.z);
    v.w = tanhf(v.w);
    *(float4*)(y + i) = v;
}

// Pad kernel: keeps the persistent kernel at OUR 4th launch (ncu slot).
__global__ void pad_kernel(unsigned v)
{
    if (threadIdx.x == 0) g_pad_sink = v;
}

__global__ void __launch_bounds__(256)
copy_kernel(const float* __restrict__ src, float* __restrict__ dst)
{
    const size_t i = ((size_t)blockIdx.x * blockDim.x + threadIdx.x) * 4;
    *(float4*)(dst + i) = *(const float4*)(src + i);
}

// ---------------------------------------------------------------------------
extern "C" void kernel_launch(void* const* d_in, const int* in_sizes, int n_in,
                              void* d_out, int out_size)
{
    const float* inputs  = (const float*)d_in[0]; // [T,B,V]
    const float* W_xh    = (const float*)d_in[1]; // [V,H]
    const float* W_hh    = (const float*)d_in[2]; // [H,H]
    const float* b_h     = (const float*)d_in[3]; // [H]
    const float* W_dense = (const float*)d_in[4]; // [H,V]
    const float* b_dense = (const float*)d_in[5]; // [V]
    float* out = (float*)d_out;

    float *xh = nullptr, *hs = nullptr;
    cudaGetSymbolAddress((void**)&xh, g_xh);
    cudaGetSymbolAddress((void**)&hs, g_hs);

    cudaFuncSetAttribute(rnn_persistent_mma,
                         cudaFuncAttributeMaxDynamicSharedMemorySize,
                         PS_SMEM);

    // Launch order: GEMM1(1), init(2), pad(3), persistent(4) <- ncu slot,
    // GEMM3(5), copy(6).

    // 1) xh = inputs @ W_xh + b_h : [65536,512] x [512,1024]
    {
        dim3 grid(H_DIM / 128, M_ALL / 128);
        sgemm_bias_kernel<<<grid, 256>>>(inputs, W_xh, b_h, xh,
                                         M_ALL, H_DIM, V_DIM);
    }

    // 2) h_0 = tanh(xh_0) + barrier reset
    init_kernel<<<BH / (256 * 4), 256>>>(xh, hs);

    // 3) pad (ncu slot alignment)
    pad_kernel<<<1, 32>>>(1u);

    // 4) all 255 recurrence steps, HMMA persistent kernel (1 barrier/step)
    rnn_persistent_mma<<<NBLK, 512, PS_SMEM>>>(W_hh, xh, hs);

    // 5) outputs = hs @ W_dense + b_dense : [65536,1024] x [1024,512]
    {
        dim3 grid(V_DIM / 128, M_ALL / 128);
        sgemm_bias_kernel<<<grid, 256>>>(hs, W_dense, b_dense, out,
                                         M_ALL, V_DIM, H_DIM);
    }

    // 6) state = h_{T-1}
    if (out_size >= TBV + BH) {
        copy_kernel<<<BH / (256 * 4), 256>>>(hs + (size_t)(T_DIM - 1) * BH,
                                             out + TBV);
    }
}

// round 13
// speedup vs baseline: 1.7609x; 1.7609x over previous
#include <cuda_runtime.h>
#include <cuda_bf16.h>
#include <math.h>
#include <stdint.h>
#include <string.h>

// Problem dims (fixed per reference)
#define T_DIM 256
#define B_DIM 256
#define V_DIM 512
#define H_DIM 1024
#define M_ALL (T_DIM * B_DIM)          // 65536
#define BH    (B_DIM * H_DIM)          // 262144
#define TBV   (T_DIM * B_DIM * V_DIM)  // 33554432

#define NBLK 128                        // 32 n-tiles x 4 b-tiles

// Scratch (allocation-free rule)
__device__ float g_xh[(size_t)M_ALL * H_DIM];        // 256 MB
__device__ float g_hs[(size_t)M_ALL * H_DIM];        // 256 MB
__device__ __nv_bfloat16 g_hhi[2 * (size_t)BH];      // parity-buffered h hi
__device__ __nv_bfloat16 g_hlo[2 * (size_t)BH];      // parity-buffered h lo
__device__ unsigned g_bar;                           // global barrier counter
__device__ unsigned g_pad_sink;                      // pad kernel target

// ---------------------------------------------------------------------------
// packed f32x2 helpers (for the SGEMM kernels)
// ---------------------------------------------------------------------------
__device__ __forceinline__ unsigned long long dup2(float v) {
    unsigned long long r;
    asm("mov.b64 %0,{%1,%1};" : "=l"(r) : "f"(v));
    return r;
}
__device__ __forceinline__ void fma2(unsigned long long& d,
                                     unsigned long long a,
                                     unsigned long long b) {
    asm("fma.rn.f32x2 %0,%1,%2,%0;" : "+l"(d) : "l"(a), "l"(b));
}
__device__ __forceinline__ float2 unpk(unsigned long long v) {
    float2 f;
    asm("mov.b64 {%0,%1},%2;" : "=f"(f.x), "=f"(f.y) : "l"(v));
    return f;
}

// ---------------------------------------------------------------------------
// bf16 / mma helpers (sm_80+ baseline PTX; safe for compute_103)
// ---------------------------------------------------------------------------
__device__ __forceinline__ uint32_t pack_bf16x2(float a, float b) {
    __nv_bfloat162 p = __floats2bfloat162_rn(a, b);
    uint32_t u;
    memcpy(&u, &p, 4);
    return u;
}

__device__ __forceinline__ void mma_bf16(float* c, const uint32_t* a,
                                         const uint32_t* b) {
    asm volatile(
        "mma.sync.aligned.m16n8k16.row.col.f32.bf16.bf16.f32 "
        "{%0,%1,%2,%3}, {%4,%5,%6,%7}, {%8,%9}, {%0,%1,%2,%3};"
        : "+f"(c[0]), "+f"(c[1]), "+f"(c[2]), "+f"(c[3])
        : "r"(a[0]), "r"(a[1]), "r"(a[2]), "r"(a[3]), "r"(b[0]), "r"(b[1]));
}

__device__ __forceinline__ void ldsm_x4(uint32_t* r, uint32_t addr) {
    asm volatile(
        "ldmatrix.sync.aligned.m8n8.x4.shared.b16 {%0,%1,%2,%3}, [%4];"
        : "=r"(r[0]), "=r"(r[1]), "=r"(r[2]), "=r"(r[3]) : "r"(addr));
}

__device__ __forceinline__ uint32_t smem_to_u32(const void* p) {
    uint32_t a;
    asm("{ .reg .u64 t; cvta.to.shared.u64 t, %1; cvt.u32.u64 %0, t; }"
        : "=r"(a) : "l"(p));
    return a;
}

// Release/acquire device-wide barrier (proven correct in R12).
__device__ __forceinline__ void grid_barrier(unsigned target)
{
    __syncthreads();
    if (threadIdx.x == 0) {
        asm volatile("red.release.gpu.add.u32 [%0], 1;"
                     :: "l"(&g_bar) : "memory");
        unsigned v;
        while (true) {
            asm volatile("ld.acquire.gpu.u32 %0, [%1];"
                         : "=r"(v) : "l"(&g_bar) : "memory");
            if (v >= target) break;
            __nanosleep(64);
        }
    }
    __syncthreads();
}

// ---------------------------------------------------------------------------
// fp32 SGEMM with f32x2 inner loop: C[M,N] = A[M,K] @ B[K,N] + bias[N]
// ---------------------------------------------------------------------------
__global__ void __launch_bounds__(256)
sgemm_bias_kernel(const float* __restrict__ A, const float* __restrict__ B,
                  const float* __restrict__ bias, float* __restrict__ C,
                  int M, int N, int K)
{
    constexpr int BM = 128, BN = 128, BK = 8, TM = 8, TN = 8;
    __shared__ __align__(16) float As[BK][BM];
    __shared__ __align__(16) float Bs[BK][BN];

    const int tid = threadIdx.x;
    const int bm = blockIdx.y * BM;
    const int bn = blockIdx.x * BN;

    const int tx = tid % (BN / TN);
    const int ty = tid / (BN / TN);
    const int row0 = ty * TM;
    const int col0 = tx * TN;

    const int aRow  = tid / (BK / 4);
    const int aCol4 = (tid % (BK / 4)) * 4;
    const int bRow  = tid / (BN / 4);
    const int bCol4 = (tid % (BN / 4)) * 4;

    const float* Aptr = A + (size_t)bm * K;
    const float* Bptr = B + bn;

    unsigned long long acc[TM][TN / 2];
#pragma unroll
    for (int i = 0; i < TM; i++)
#pragma unroll
        for (int j = 0; j < TN / 2; j++) acc[i][j] = 0ull;

    for (int k0 = 0; k0 < K; k0 += BK) {
        float4 a4 = *(const float4*)(Aptr + (size_t)aRow * K + k0 + aCol4);
        As[aCol4 + 0][aRow] = a4.x;
        As[aCol4 + 1][aRow] = a4.y;
        As[aCol4 + 2][aRow] = a4.z;
        As[aCol4 + 3][aRow] = a4.w;
        *(float4*)&Bs[bRow][bCol4] =
            *(const float4*)(Bptr + (size_t)(k0 + bRow) * N + bCol4);
        __syncthreads();

#pragma unroll
        for (int k = 0; k < BK; k++) {
            unsigned long long ra[TM];
#pragma unroll
            for (int i = 0; i < TM; i++) ra[i] = dup2(As[k][row0 + i]);
            const ulonglong2* bp = (const ulonglong2*)&Bs[k][col0];
            ulonglong2 rb0 = bp[0];
            ulonglong2 rb1 = bp[1];
#pragma unroll
            for (int i = 0; i < TM; i++) {
                fma2(acc[i][0], ra[i], rb0.x);
                fma2(acc[i][1], ra[i], rb0.y);
                fma2(acc[i][2], ra[i], rb1.x);
                fma2(acc[i][3], ra[i], rb1.y);
            }
        }
        __syncthreads();
    }

    float4 bv0 = *(const float4*)(bias + bn + col0);
    float4 bv1 = *(const float4*)(bias + bn + col0 + 4);
#pragma unroll
    for (int i = 0; i < TM; i++) {
        const size_t gr = (size_t)(bm + row0 + i);
        float2 a0 = unpk(acc[i][0]);
        float2 a1 = unpk(acc[i][1]);
        float2 a2 = unpk(acc[i][2]);
        float2 a3 = unpk(acc[i][3]);
        float4 v0 = make_float4(a0.x + bv0.x, a0.y + bv0.y,
                                a1.x + bv0.z, a1.y + bv0.w);
        float4 v1 = make_float4(a2.x + bv1.x, a2.y + bv1.y,
                                a3.x + bv1.z, a3.y + bv1.w);
        *(float4*)(C + gr * N + bn + col0)     = v0;
        *(float4*)(C + gr * N + bn + col0 + 4) = v1;
    }
}

// ---------------------------------------------------------------------------
// Persistent HMMA recurrence — NO split-K, ONE barrier per step.
// 128 blocks = 32 nt x 4 bt. Block tile: 64 b x 32 n x FULL k=1024.
// Smem: W slice [32n][1024k] bf16 hi+lo RESIDENT (129 KB, split once);
//       h chunks [64b][128k] hi/lo double-buffered (68 KB).
// h lives in gmem as parity-buffered bf16 hi/lo (written by owner epilogue).
// Step tt: stream h chunks + mma (2 acc sets over even/odd k32) ->
//          epilogue (+xh, tanh, write hs fp32 + bf16 hi/lo parity tt&1) ->
//          one release/acquire grid barrier.
// ---------------------------------------------------------------------------
#define WRS     516                       // W row stride (words); 516%32=4
#define W_WORDS (32 * WRS)                // 16512 words per W buffer
#define HST     68                        // h chunk row stride (words); 68%32=4
#define H_WORDS (64 * HST)                // 4352 words per h chunk buffer
#define PS_SMEM ((2 * W_WORDS + 4 * H_WORDS) * 4)   // 201,728 B

__global__ void __launch_bounds__(512, 1)
rnn_persistent_mma(const float* __restrict__ W,
                   const float* __restrict__ xh,
                   float* __restrict__ hs)
{
    extern __shared__ __align__(16) uint32_t smw[];
    uint32_t* Whi  = smw;                       // [32n][WRS]
    uint32_t* Wlo  = smw + W_WORDS;
    uint32_t* Hbuf = smw + 2 * W_WORDS;         // [dbuf][hi/lo][H_WORDS]

    const uint32_t sW = smem_to_u32(Whi);
    const uint32_t sH = sW + 2 * W_WORDS * 4;

    const int tid  = threadIdx.x;
    const int wid  = tid >> 5;
    const int lane = tid & 31;
    const int bx   = blockIdx.x;
    const int nt   = bx >> 2;         // 0..31
    const int bt   = bx & 3;          // 0..3
    const int n0   = nt * 32;
    const int b0   = bt * 64;

    const int g = lane >> 2;          // 0..7
    const int t = lane & 3;           // 0..3

    // warp tile: 16 b x 8 n.  wm 0..3, wn 0..3.
    const int wm = wid & 3;
    const int wn = wid >> 2;

    // A (h) ldmatrix lane base: m16k16 x4 (two per k32)
    const int aRow = wm * 16 + (lane & 15);
    const uint32_t aOffW = (uint32_t)aRow * HST + ((lane >> 4) << 2);
    // B (W) ldmatrix lane base: n8k32 x4 (4 k-tiles along k)
    const int bRow = wn * 8 + (lane & 7);
    const uint32_t bHiBase =
        sW + ((uint32_t)bRow * WRS + (((lane >> 3) & 3) << 2)) * 4;
    const uint32_t bLoBase = bHiBase + W_WORDS * 4;

    // ---- one-time: split W slice [1024k][32n] -> smem [32n][1024k] hi/lo ----
    for (int idx = tid; idx < 32 * 512; idx += 512) {
        const int n = idx & 31;
        const int c = idx >> 5;       // k-pair 0..511
        const float w0 = W[(size_t)(2 * c)     * H_DIM + n0 + n];
        const float w1 = W[(size_t)(2 * c + 1) * H_DIM + n0 + n];
        const float h0 = __bfloat162float(__float2bfloat16(w0));
        const float h1 = __bfloat162float(__float2bfloat16(w1));
        Whi[n * WRS + c] = pack_bf16x2(w0, w1);
        Wlo[n * WRS + c] = pack_bf16x2(w0 - h0, w1 - h1);
    }

    // epilogue ownership (fixed per thread)
    const int er0 = b0 + wm * 16 + g;
    const int ec  = n0 + wn * 8 + 2 * t;

    __syncthreads();

    for (int tt = 1; tt < T_DIM; tt++) {
        const int p = (tt - 1) & 1;   // read parity
        const __nv_bfloat16* hh = g_hhi + (size_t)p * BH;
        const __nv_bfloat16* hl = g_hlo + (size_t)p * BH;

        float accA[4] = {0.f, 0.f, 0.f, 0.f};
        float accB[4] = {0.f, 0.f, 0.f, 0.f};

        // ---- stage chunk 0 ----
        uint4 v[4];
#pragma unroll
        for (int i = 0; i < 4; i++) {
            const int idx = tid + i * 512;
            const int bufsel = idx >> 10;           // 0=hi, 1=lo
            const int row = (idx >> 4) & 63;
            const int seg = idx & 15;
            const __nv_bfloat16* src = (bufsel ? hl : hh)
                + (size_t)(b0 + row) * H_DIM + seg * 8;
            v[i] = *(const uint4*)src;
        }
#pragma unroll
        for (int i = 0; i < 4; i++) {
            const int idx = tid + i * 512;
            const int bufsel = idx >> 10;
            const int row = (idx >> 4) & 63;
            const int seg = idx & 15;
            *(uint4*)&Hbuf[(size_t)bufsel * H_WORDS + row * HST + seg * 4] = v[i];
        }
        __syncthreads();

        for (int c = 0; c < 8; c++) {
            const int d = c & 1;
            if (c < 7) {
#pragma unroll
                for (int i = 0; i < 4; i++) {
                    const int idx = tid + i * 512;
                    const int bufsel = idx >> 10;
                    const int row = (idx >> 4) & 63;
                    const int seg = idx & 15;
                    const __nv_bfloat16* src = (bufsel ? hl : hh)
                        + (size_t)(b0 + row) * H_DIM + (c + 1) * 128 + seg * 8;
                    v[i] = *(const uint4*)src;
                }
            }

            const uint32_t aHiB = sH + ((uint32_t)(d * 2) * H_WORDS + aOffW) * 4;
            const uint32_t aLoB = aHiB + H_WORDS * 4;
#pragma unroll
            for (int j = 0; j < 4; j++) {
                const int kc = c * 4 + j;           // global k32 index
                uint32_t ah0[4], ah1[4], al0[4], al1[4], bh[4], bl[4];
                ldsm_x4(ah0, aHiB + j * 64);
                ldsm_x4(ah1, aHiB + j * 64 + 32);
                ldsm_x4(al0, aLoB + j * 64);
                ldsm_x4(al1, aLoB + j * 64 + 32);
                ldsm_x4(bh, bHiBase + kc * 64);
                ldsm_x4(bl, bLoBase + kc * 64);
                float* A = (j & 1) ? accB : accA;
                mma_bf16(A, ah0, bh);       // k-step0: hi*hi
                mma_bf16(A, ah0, bl);       //          hi*lo
                mma_bf16(A, al0, bh);       //          lo*hi
                mma_bf16(A, ah1, bh + 2);   // k-step1: hi*hi
                mma_bf16(A, ah1, bl + 2);   //          hi*lo
                mma_bf16(A, al1, bh + 2);   //          lo*hi
            }

            if (c < 7) {
                const int dn = 1 - d;
#pragma unroll
                for (int i = 0; i < 4; i++) {
                    const int idx = tid + i * 512;
                    const int bufsel = idx >> 10;
                    const int row = (idx >> 4) & 63;
                    const int seg = idx & 15;
                    *(uint4*)&Hbuf[(size_t)(dn * 2 + bufsel) * H_WORDS
                                   + row * HST + seg * 4] = v[i];
                }
            }
            __syncthreads();
        }

        // ---- epilogue: +xh, tanh, write hs fp32 + bf16 hi/lo (parity tt&1) --
        {
            const float* xr = xh + (size_t)tt * BH;
            float2 x0 = *(const float2*)(xr + (size_t)er0 * H_DIM + ec);
            float2 x1 = *(const float2*)(xr + (size_t)(er0 + 8) * H_DIM + ec);
            const float o00 = tanhf(accA[0] + accB[0] + x0.x);
            const float o01 = tanhf(accA[1] + accB[1] + x0.y);
            const float o10 = tanhf(accA[2] + accB[2] + x1.x);
            const float o11 = tanhf(accA[3] + accB[3] + x1.y);

            float* ho = hs + (size_t)tt * BH;
            *(float2*)(ho + (size_t)er0 * H_DIM + ec) = make_float2(o00, o01);
            *(float2*)(ho + (size_t)(er0 + 8) * H_DIM + ec) = make_float2(o10, o11);

            const int q = tt & 1;
            __nv_bfloat16* dhh = g_hhi + (size_t)q * BH;
            __nv_bfloat16* dhl = g_hlo + (size_t)q * BH;
            const float h00 = __bfloat162float(__float2bfloat16(o00));
            const float h01 = __bfloat162float(__float2bfloat16(o01));
            const float h10 = __bfloat162float(__float2bfloat16(o10));
            const float h11 = __bfloat162float(__float2bfloat16(o11));
            *(uint32_t*)(dhh + (size_t)er0 * H_DIM + ec) = pack_bf16x2(o00, o01);
            *(uint32_t*)(dhh + (size_t)(er0 + 8) * H_DIM + ec) = pack_bf16x2(o10, o11);
            *(uint32_t*)(dhl + (size_t)er0 * H_DIM + ec) =
                pack_bf16x2(o00 - h00, o01 - h01);
            *(uint32_t*)(dhl + (size_t)(er0 + 8) * H_DIM + ec) =
                pack_bf16x2(o10 - h10, o11 - h11);
        }

        // ---- single device barrier per step ----
        if (tt < T_DIM - 1) grid_barrier((unsigned)tt * NBLK);
    }
}

// h_0 = tanh(xh_0): write fp32 hs[0] + bf16 hi/lo parity-0; reset barrier.
__global__ void __launch_bounds__(256)
init_kernel(const float* __restrict__ x, float* __restrict__ y)
{
    if (blockIdx.x == 0 && threadIdx.x == 0) g_bar = 0u;
    const size_t i = ((size_t)blockIdx.x * blockDim.x + threadIdx.x) * 4;
    float4 v = *(const float4*)(x + i);
    v.x = tanhf(v.x);
    v.y = tanhf(v.y);
    v.z = tanhf(v.z);
    v.w = tanhf(v.w);
    *(float4*)(y + i) = v;
    const float hx = __bfloat162float(__float2bfloat16(v.x));
    const float hy = __bfloat162float(__float2bfloat16(v.y));
    const float hz = __bfloat162float(__float2bfloat16(v.z));
    const float hw = __bfloat162float(__float2bfloat16(v.w));
    *(uint2*)(g_hhi + i) = make_uint2(pack_bf16x2(v.x, v.y),
                                      pack_bf16x2(v.z, v.w));
    *(uint2*)(g_hlo + i) = make_uint2(pack_bf16x2(v.x - hx, v.y - hy),
                                      pack_bf16x2(v.z - hz, v.w - hw));
}

// Pad kernel: keeps the persistent kernel at OUR 4th launch (ncu slot).
__global__ void pad_kernel(unsigned v)
{
    if (threadIdx.x == 0) g_pad_sink = v;
}

__global__ void __launch_bounds__(256)
copy_kernel(const float* __restrict__ src, float* __restrict__ dst)
{
    const size_t i = ((size_t)blockIdx.x * blockDim.x + threadIdx.x) * 4;
    *(float4*)(dst + i) = *(const float4*)(src + i);
}

// ---------------------------------------------------------------------------
extern "C" void kernel_launch(void* const* d_in, const int* in_sizes, int n_in,
                              void* d_out, int out_size)
{
    const float* inputs  = (const float*)d_in[0]; // [T,B,V]
    const float* W_xh    = (const float*)d_in[1]; // [V,H]
    const float* W_hh    = (const float*)d_in[2]; // [H,H]
    const float* b_h     = (const float*)d_in[3]; // [H]
    const float* W_dense = (const float*)d_in[4]; // [H,V]
    const float* b_dense = (const float*)d_in[5]; // [V]
    float* out = (float*)d_out;

    float *xh = nullptr, *hs = nullptr;
    cudaGetSymbolAddress((void**)&xh, g_xh);
    cudaGetSymbolAddress((void**)&hs, g_hs);

    cudaFuncSetAttribute(rnn_persistent_mma,
                         cudaFuncAttributeMaxDynamicSharedMemorySize,
                         PS_SMEM);

    // Launch order: GEMM1(1), init(2), pad(3), persistent(4) <- ncu slot,
    // GEMM3(5), copy(6).

    // 1) xh = inputs @ W_xh + b_h : [65536,512] x [512,1024]
    {
        dim3 grid(H_DIM / 128, M_ALL / 128);
        sgemm_bias_kernel<<<grid, 256>>>(inputs, W_xh, b_h, xh,
                                         M_ALL, H_DIM, V_DIM);
    }

    // 2) h_0 = tanh(xh_0) + bf16 split + barrier reset
    init_kernel<<<BH / (256 * 4), 256>>>(xh, hs);

    // 3) pad (ncu slot alignment)
    pad_kernel<<<1, 32>>>(1u);

    // 4) all 255 recurrence steps (no split-K, one barrier/step)
    rnn_persistent_mma<<<NBLK, 512, PS_SMEM>>>(W_hh, xh, hs);

    // 5) outputs = hs @ W_dense + b_dense : [65536,1024] x [1024,512]
    {
        dim3 grid(V_DIM / 128, M_ALL / 128);
        sgemm_bias_kernel<<<grid, 256>>>(hs, W_dense, b_dense, out,
                                         M_ALL, V_DIM, H_DIM);
    }

    // 6) state = h_{T-1}
    if (out_size >= TBV + BH) {
        copy_kernel<<<BH / (256 * 4), 256>>>(hs + (size_t)(T_DIM - 1) * BH,
                                             out + TBV);
    }
}

// round 14
// speedup vs baseline: 1.8256x; 1.0367x over previous
#include <cuda_runtime.h>
#include <cuda_bf16.h>
#include <math.h>
#include <stdint.h>
#include <string.h>

// Problem dims (fixed per reference)
#define T_DIM 256
#define B_DIM 256
#define V_DIM 512
#define H_DIM 1024
#define M_ALL (T_DIM * B_DIM)          // 65536
#define BH    (B_DIM * H_DIM)          // 262144
#define TBV   (T_DIM * B_DIM * V_DIM)  // 33554432

#define NBLK 128                        // 32 n-tiles x 4 b-tiles

// Scratch (allocation-free rule)
__device__ float g_xh[(size_t)M_ALL * H_DIM];        // 256 MB
__device__ float g_hs[(size_t)M_ALL * H_DIM];        // 256 MB
__device__ __nv_bfloat16 g_hhi[2 * (size_t)BH];      // parity-buffered h hi
__device__ __nv_bfloat16 g_hlo[2 * (size_t)BH];      // parity-buffered h lo
__device__ unsigned g_bar;                           // global barrier counter
__device__ unsigned g_pad_sink;                      // pad kernel target

// ---------------------------------------------------------------------------
// packed f32x2 helpers (for the SGEMM kernels)
// ---------------------------------------------------------------------------
__device__ __forceinline__ unsigned long long dup2(float v) {
    unsigned long long r;
    asm("mov.b64 %0,{%1,%1};" : "=l"(r) : "f"(v));
    return r;
}
__device__ __forceinline__ void fma2(unsigned long long& d,
                                     unsigned long long a,
                                     unsigned long long b) {
    asm("fma.rn.f32x2 %0,%1,%2,%0;" : "+l"(d) : "l"(a), "l"(b));
}
__device__ __forceinline__ float2 unpk(unsigned long long v) {
    float2 f;
    asm("mov.b64 {%0,%1},%2;" : "=f"(f.x), "=f"(f.y) : "l"(v));
    return f;
}

// ---------------------------------------------------------------------------
// bf16 / mma helpers (sm_80+ baseline PTX; safe for compute_103)
// ---------------------------------------------------------------------------
__device__ __forceinline__ uint32_t pack_bf16x2(float a, float b) {
    __nv_bfloat162 p = __floats2bfloat162_rn(a, b);
    uint32_t u;
    memcpy(&u, &p, 4);
    return u;
}

__device__ __forceinline__ void mma_bf16(float* c, const uint32_t* a,
                                         const uint32_t* b) {
    asm volatile(
        "mma.sync.aligned.m16n8k16.row.col.f32.bf16.bf16.f32 "
        "{%0,%1,%2,%3}, {%4,%5,%6,%7}, {%8,%9}, {%0,%1,%2,%3};"
        : "+f"(c[0]), "+f"(c[1]), "+f"(c[2]), "+f"(c[3])
        : "r"(a[0]), "r"(a[1]), "r"(a[2]), "r"(a[3]), "r"(b[0]), "r"(b[1]));
}

__device__ __forceinline__ void ldsm_x4(uint32_t* r, uint32_t addr) {
    asm volatile(
        "ldmatrix.sync.aligned.m8n8.x4.shared.b16 {%0,%1,%2,%3}, [%4];"
        : "=r"(r[0]), "=r"(r[1]), "=r"(r[2]), "=r"(r[3]) : "r"(addr));
}

__device__ __forceinline__ uint32_t smem_to_u32(const void* p) {
    uint32_t a;
    asm("{ .reg .u64 t; cvta.to.shared.u64 t, %1; cvt.u32.u64 %0, t; }"
        : "=r"(a) : "l"(p));
    return a;
}

// Release/acquire device-wide barrier (proven correct R12/R13).
__device__ __forceinline__ void grid_barrier(unsigned target)
{
    __syncthreads();
    if (threadIdx.x == 0) {
        asm volatile("red.release.gpu.add.u32 [%0], 1;"
                     :: "l"(&g_bar) : "memory");
        unsigned v;
        while (true) {
            asm volatile("ld.acquire.gpu.u32 %0, [%1];"
                         : "=r"(v) : "l"(&g_bar) : "memory");
            if (v >= target) break;
            __nanosleep(64);
        }
    }
    __syncthreads();
}

// ---------------------------------------------------------------------------
// fp32 SGEMM with f32x2 inner loop: C[M,N] = A[M,K] @ B[K,N] + bias[N]
// ---------------------------------------------------------------------------
__global__ void __launch_bounds__(256)
sgemm_bias_kernel(const float* __restrict__ A, const float* __restrict__ B,
                  const float* __restrict__ bias, float* __restrict__ C,
                  int M, int N, int K)
{
    constexpr int BM = 128, BN = 128, BK = 8, TM = 8, TN = 8;
    __shared__ __align__(16) float As[BK][BM];
    __shared__ __align__(16) float Bs[BK][BN];

    const int tid = threadIdx.x;
    const int bm = blockIdx.y * BM;
    const int bn = blockIdx.x * BN;

    const int tx = tid % (BN / TN);
    const int ty = tid / (BN / TN);
    const int row0 = ty * TM;
    const int col0 = tx * TN;

    const int aRow  = tid / (BK / 4);
    const int aCol4 = (tid % (BK / 4)) * 4;
    const int bRow  = tid / (BN / 4);
    const int bCol4 = (tid % (BN / 4)) * 4;

    const float* Aptr = A + (size_t)bm * K;
    const float* Bptr = B + bn;

    unsigned long long acc[TM][TN / 2];
#pragma unroll
    for (int i = 0; i < TM; i++)
#pragma unroll
        for (int j = 0; j < TN / 2; j++) acc[i][j] = 0ull;

    for (int k0 = 0; k0 < K; k0 += BK) {
        float4 a4 = *(const float4*)(Aptr + (size_t)aRow * K + k0 + aCol4);
        As[aCol4 + 0][aRow] = a4.x;
        As[aCol4 + 1][aRow] = a4.y;
        As[aCol4 + 2][aRow] = a4.z;
        As[aCol4 + 3][aRow] = a4.w;
        *(float4*)&Bs[bRow][bCol4] =
            *(const float4*)(Bptr + (size_t)(k0 + bRow) * N + bCol4);
        __syncthreads();

#pragma unroll
        for (int k = 0; k < BK; k++) {
            unsigned long long ra[TM];
#pragma unroll
            for (int i = 0; i < TM; i++) ra[i] = dup2(As[k][row0 + i]);
            const ulonglong2* bp = (const ulonglong2*)&Bs[k][col0];
            ulonglong2 rb0 = bp[0];
            ulonglong2 rb1 = bp[1];
#pragma unroll
            for (int i = 0; i < TM; i++) {
                fma2(acc[i][0], ra[i], rb0.x);
                fma2(acc[i][1], ra[i], rb0.y);
                fma2(acc[i][2], ra[i], rb1.x);
                fma2(acc[i][3], ra[i], rb1.y);
            }
        }
        __syncthreads();
    }

    float4 bv0 = *(const float4*)(bias + bn + col0);
    float4 bv1 = *(const float4*)(bias + bn + col0 + 4);
#pragma unroll
    for (int i = 0; i < TM; i++) {
        const size_t gr = (size_t)(bm + row0 + i);
        float2 a0 = unpk(acc[i][0]);
        float2 a1 = unpk(acc[i][1]);
        float2 a2 = unpk(acc[i][2]);
        float2 a3 = unpk(acc[i][3]);
        float4 v0 = make_float4(a0.x + bv0.x, a0.y + bv0.y,
                                a1.x + bv0.z, a1.y + bv0.w);
        float4 v1 = make_float4(a2.x + bv1.x, a2.y + bv1.y,
                                a3.x + bv1.z, a3.y + bv1.w);
        *(float4*)(C + gr * N + bn + col0)     = v0;
        *(float4*)(C + gr * N + bn + col0 + 4) = v1;
    }
}

// ---------------------------------------------------------------------------
// Persistent HMMA recurrence — no split-K across blocks, ONE barrier/step,
// warp-level intra-block k-split to cut smem-read redundancy.
// 128 blocks = 32 nt x 4 bt. Block tile: 64 b x 32 n x full k=1024.
// 16 warps = 4 wm (16 b-rows) x 2 wn (16 n-cols) x 2 wk (512-k halves).
// Smem: W slice [32n][1024k] bf16 hi+lo RESIDENT (129 KB);
//       h chunks [64b][128k] hi/lo double-buffered (68 KB; also reused as
//       the 16 KB k-reduction scratch after the chunk loop).
// Per k16 per warp: 4 ldsm.x4 (A hi/lo m16k16, B hi/lo n16k16) + 6 mma
// (3 bf16-split products x 2 n8). Fragments double-buffered across j;
// j-parity acc sets. End of step: wk1 -> smem scratch, wk0 adds + epilogue
// (+xh, tanh, hs fp32 + parity bf16 hi/lo), then grid barrier.
// ---------------------------------------------------------------------------
#define WRS     516                       // W row stride (words); 516%32=4
#define W_WORDS (32 * WRS)
#define HST     68                        // h chunk row stride (words)
#define H_WORDS (64 * HST)
#define PS_SMEM ((2 * W_WORDS + 4 * H_WORDS) * 4)   // 201,728 B

__global__ void __launch_bounds__(512, 1)
rnn_persistent_mma(const float* __restrict__ W,
                   const float* __restrict__ xh,
                   float* __restrict__ hs)
{
    extern __shared__ __align__(16) uint32_t smw[];
    uint32_t* Whi  = smw;                       // [32n][WRS]
    uint32_t* Wlo  = smw + W_WORDS;
    uint32_t* Hbuf = smw + 2 * W_WORDS;         // [dbuf][hi/lo][H_WORDS]
    float*    Red  = (float*)Hbuf;              // reduction scratch (16 KB)

    const uint32_t sW = smem_to_u32(Whi);
    const uint32_t sH = sW + 2 * W_WORDS * 4;

    const int tid  = threadIdx.x;
    const int wid  = tid >> 5;
    const int lane = tid & 31;
    const int bx   = blockIdx.x;
    const int nt   = bx >> 2;         // 0..31
    const int bt   = bx & 3;          // 0..3
    const int n0   = nt * 32;
    const int b0   = bt * 64;

    const int g = lane >> 2;          // 0..7
    const int t = lane & 3;           // 0..3

    // warp grid: wm (16 b-rows), wn (16 n-cols), wk (k half)
    const int wm = wid & 3;
    const int wn = (wid >> 2) & 1;
    const int wk = wid >> 3;

    // A (h) ldmatrix lane base within a chunk buffer (m16k16 x4)
    const int aRow = wm * 16 + (lane & 15);
    const uint32_t aOff = (uint32_t)aRow * HST + ((lane >> 4) << 2);
    // B (W) ldmatrix lane base (n16k16 x4): lanes 0-7 n0-7/k0, 8-15 n0-7/k16B,
    // 16-23 n8-15/k0, 24-31 n8-15/k16B
    const int bRow = wn * 16 + ((lane >> 4) << 3) + (lane & 7);
    const uint32_t bHiBase =
        sW + ((uint32_t)bRow * WRS + (((lane >> 3) & 1) << 2)) * 4;
    const uint32_t bLoBase = bHiBase + W_WORDS * 4;

    // ---- one-time: split W slice [1024k][32n] -> smem [32n][1024k] hi/lo ----
    for (int idx = tid; idx < 32 * 512; idx += 512) {
        const int n = idx & 31;
        const int c = idx >> 5;       // k-pair 0..511
        const float w0 = W[(size_t)(2 * c)     * H_DIM + n0 + n];
        const float w1 = W[(size_t)(2 * c + 1) * H_DIM + n0 + n];
        const float h0 = __bfloat162float(__float2bfloat16(w0));
        const float h1 = __bfloat162float(__float2bfloat16(w1));
        Whi[n * WRS + c] = pack_bf16x2(w0, w1);
        Wlo[n * WRS + c] = pack_bf16x2(w0 - h0, w1 - h1);
    }

    // epilogue ownership (wk0 warps): rows er0, er0+8; cols per nn8 group
    const int er0 = b0 + wm * 16 + g;
    const int ecb = n0 + wn * 16 + 2 * t;     // + nn*8

    __syncthreads();

    for (int tt = 1; tt < T_DIM; tt++) {
        const int p = (tt - 1) & 1;   // read parity
        const __nv_bfloat16* hh = g_hhi + (size_t)p * BH;
        const __nv_bfloat16* hl = g_hlo + (size_t)p * BH;

        // acc[jpar][nn8][4]
        float acc[2][2][4];
#pragma unroll
        for (int a = 0; a < 2; a++)
#pragma unroll
            for (int b = 0; b < 2; b++)
#pragma unroll
                for (int i = 0; i < 4; i++) acc[a][b][i] = 0.0f;

        // ---- stage chunk 0 ----
        uint4 v[4];
#pragma unroll
        for (int i = 0; i < 4; i++) {
            const int idx = tid + i * 512;
            const int bufsel = idx >> 10;           // 0=hi, 1=lo
            const int row = (idx >> 4) & 63;
            const int seg = idx & 15;
            const __nv_bfloat16* src = (bufsel ? hl : hh)
                + (size_t)(b0 + row) * H_DIM + seg * 8;
            v[i] = *(const uint4*)src;
        }
#pragma unroll
        for (int i = 0; i < 4; i++) {
            const int idx = tid + i * 512;
            const int bufsel = idx >> 10;
            const int row = (idx >> 4) & 63;
            const int seg = idx & 15;
            *(uint4*)&Hbuf[(size_t)bufsel * H_WORDS + row * HST + seg * 4] = v[i];
        }
        __syncthreads();

        for (int c = 0; c < 8; c++) {
            const int d = c & 1;
            if (c < 7) {
#pragma unroll
                for (int i = 0; i < 4; i++) {
                    const int idx = tid + i * 512;
                    const int bufsel = idx >> 10;
                    const int row = (idx >> 4) & 63;
                    const int seg = idx & 15;
                    const __nv_bfloat16* src = (bufsel ? hl : hh)
                        + (size_t)(b0 + row) * H_DIM + (c + 1) * 128 + seg * 8;
                    v[i] = *(const uint4*)src;
                }
            }

            // A base for this chunk buffer + this warp's k-half
            const uint32_t aHi = sH + ((uint32_t)(d * 2) * H_WORDS + aOff) * 4
                               + (uint32_t)wk * 128;
            const uint32_t aLo = aHi + H_WORDS * 4;
            // B base for this chunk's global k-range + warp's k-half
            const uint32_t kb = (uint32_t)(c * 8 + wk * 4) * 32;

            // double-buffered fragments across j
            uint32_t ah[2][4], al[2][4], bh[2][4], bl[2][4];
            ldsm_x4(ah[0], aHi);
            ldsm_x4(al[0], aLo);
            ldsm_x4(bh[0], bHiBase + kb);
            ldsm_x4(bl[0], bLoBase + kb);
#pragma unroll
            for (int j = 0; j < 4; j++) {
                const int cur = j & 1;
                const int nxt = cur ^ 1;
                if (j < 3) {
                    ldsm_x4(ah[nxt], aHi + (j + 1) * 32);
                    ldsm_x4(al[nxt], aLo + (j + 1) * 32);
                    ldsm_x4(bh[nxt], bHiBase + kb + (j + 1) * 32);
                    ldsm_x4(bl[nxt], bLoBase + kb + (j + 1) * 32);
                }
                float* c0 = acc[cur][0];
                float* c1 = acc[cur][1];
                mma_bf16(c0, ah[cur], bh[cur]);         // n0-7 hi*hi
                mma_bf16(c1, ah[cur], bh[cur] + 2);     // n8-15 hi*hi
                mma_bf16(c0, ah[cur], bl[cur]);         // hi*lo
                mma_bf16(c1, ah[cur], bl[cur] + 2);
                mma_bf16(c0, al[cur], bh[cur]);         // lo*hi
                mma_bf16(c1, al[cur], bh[cur] + 2);
            }

            if (c < 7) {
                const int dn = 1 - d;
#pragma unroll
                for (int i = 0; i < 4; i++) {
                    const int idx = tid + i * 512;
                    const int bufsel = idx >> 10;
                    const int row = (idx >> 4) & 63;
                    const int seg = idx & 15;
                    *(uint4*)&Hbuf[(size_t)(dn * 2 + bufsel) * H_WORDS
                                   + row * HST + seg * 4] = v[i];
                }
            }
            __syncthreads();
        }

        // ---- intra-block k-reduction: wk1 -> scratch, wk0 adds ----
        if (wk == 1) {
            float* dst = Red + (size_t)((wid & 7) * 4) * 128 + lane * 4;
#pragma unroll
            for (int a = 0; a < 2; a++)
#pragma unroll
                for (int b = 0; b < 2; b++)
                    *(float4*)(dst + (a * 2 + b) * 128) =
                        make_float4(acc[a][b][0], acc[a][b][1],
                                    acc[a][b][2], acc[a][b][3]);
        }
        __syncthreads();

        if (wk == 0) {
            const float* srcr = Red + (size_t)((wid & 7) * 4) * 128 + lane * 4;
            float fin[2][4];
#pragma unroll
            for (int b = 0; b < 2; b++) {
                float4 r0 = *(const float4*)(srcr + (0 * 2 + b) * 128);
                float4 r1 = *(const float4*)(srcr + (1 * 2 + b) * 128);
                fin[b][0] = acc[0][b][0] + acc[1][b][0] + r0.x + r1.x;
                fin[b][1] = acc[0][b][1] + acc[1][b][1] + r0.y + r1.y;
                fin[b][2] = acc[0][b][2] + acc[1][b][2] + r0.z + r1.z;
                fin[b][3] = acc[0][b][3] + acc[1][b][3] + r0.w + r1.w;
            }

            // ---- epilogue: +xh, tanh, hs fp32 + parity bf16 hi/lo ----
            const float* xr = xh + (size_t)tt * BH;
            float* ho = hs + (size_t)tt * BH;
            const int q = tt & 1;
            __nv_bfloat16* dhh = g_hhi + (size_t)q * BH;
            __nv_bfloat16* dhl = g_hlo + (size_t)q * BH;
#pragma unroll
            for (int b = 0; b < 2; b++) {
                const int ec = ecb + b * 8;
                float2 x0 = *(const float2*)(xr + (size_t)er0 * H_DIM + ec);
                float2 x1 = *(const float2*)(xr + (size_t)(er0 + 8) * H_DIM + ec);
                const float o00 = tanhf(fin[b][0] + x0.x);
                const float o01 = tanhf(fin[b][1] + x0.y);
                const float o10 = tanhf(fin[b][2] + x1.x);
                const float o11 = tanhf(fin[b][3] + x1.y);
                *(float2*)(ho + (size_t)er0 * H_DIM + ec) = make_float2(o00, o01);
                *(float2*)(ho + (size_t)(er0 + 8) * H_DIM + ec) =
                    make_float2(o10, o11);
                const float h00 = __bfloat162float(__float2bfloat16(o00));
                const float h01 = __bfloat162float(__float2bfloat16(o01));
                const float h10 = __bfloat162float(__float2bfloat16(o10));
                const float h11 = __bfloat162float(__float2bfloat16(o11));
                *(uint32_t*)(dhh + (size_t)er0 * H_DIM + ec) =
                    pack_bf16x2(o00, o01);
                *(uint32_t*)(dhh + (size_t)(er0 + 8) * H_DIM + ec) =
                    pack_bf16x2(o10, o11);
                *(uint32_t*)(dhl + (size_t)er0 * H_DIM + ec) =
                    pack_bf16x2(o00 - h00, o01 - h01);
                *(uint32_t*)(dhl + (size_t)(er0 + 8) * H_DIM + ec) =
                    pack_bf16x2(o10 - h10, o11 - h11);
            }
        }

        // ---- single device barrier per step ----
        if (tt < T_DIM - 1) grid_barrier((unsigned)tt * NBLK);
    }
}

// h_0 = tanh(xh_0): write fp32 hs[0] + bf16 hi/lo parity-0; reset barrier.
__global__ void __launch_bounds__(256)
init_kernel(const float* __restrict__ x, float* __restrict__ y)
{
    if (blockIdx.x == 0 && threadIdx.x == 0) g_bar = 0u;
    const size_t i = ((size_t)blockIdx.x * blockDim.x + threadIdx.x) * 4;
    float4 v = *(const float4*)(x + i);
    v.x = tanhf(v.x);
    v.y = tanhf(v.y);
    v.z = tanhf(v.z);
    v.w = tanhf(v.w);
    *(float4*)(y + i) = v;
    const float hx = __bfloat162float(__float2bfloat16(v.x));
    const float hy = __bfloat162float(__float2bfloat16(v.y));
    const float hz = __bfloat162float(__float2bfloat16(v.z));
    const float hw = __bfloat162float(__float2bfloat16(v.w));
    *(uint2*)(g_hhi + i) = make_uint2(pack_bf16x2(v.x, v.y),
                                      pack_bf16x2(v.z, v.w));
    *(uint2*)(g_hlo + i) = make_uint2(pack_bf16x2(v.x - hx, v.y - hy),
                                      pack_bf16x2(v.z - hz, v.w - hw));
}

// Pad kernel: keeps the persistent kernel at OUR 4th launch (ncu slot).
__global__ void pad_kernel(unsigned v)
{
    if (threadIdx.x == 0) g_pad_sink = v;
}

__global__ void __launch_bounds__(256)
copy_kernel(const float* __restrict__ src, float* __restrict__ dst)
{
    const size_t i = ((size_t)blockIdx.x * blockDim.x + threadIdx.x) * 4;
    *(float4*)(dst + i) = *(const float4*)(src + i);
}

// ---------------------------------------------------------------------------
extern "C" void kernel_launch(void* const* d_in, const int* in_sizes, int n_in,
                              void* d_out, int out_size)
{
    const float* inputs  = (const float*)d_in[0]; // [T,B,V]
    const float* W_xh    = (const float*)d_in[1]; // [V,H]
    const float* W_hh    = (const float*)d_in[2]; // [H,H]
    const float* b_h     = (const float*)d_in[3]; // [H]
    const float* W_dense = (const float*)d_in[4]; // [H,V]
    const float* b_dense = (const float*)d_in[5]; // [V]
    float* out = (float*)d_out;

    float *xh = nullptr, *hs = nullptr;
    cudaGetSymbolAddress((void**)&xh, g_xh);
    cudaGetSymbolAddress((void**)&hs, g_hs);

    cudaFuncSetAttribute(rnn_persistent_mma,
                         cudaFuncAttributeMaxDynamicSharedMemorySize,
                         PS_SMEM);

    // Launch order: GEMM1(1), init(2), pad(3), persistent(4) <- ncu slot,
    // GEMM3(5), copy(6).

    // 1) xh = inputs @ W_xh + b_h : [65536,512] x [512,1024]
    {
        dim3 grid(H_DIM / 128, M_ALL / 128);
        sgemm_bias_kernel<<<grid, 256>>>(inputs, W_xh, b_h, xh,
                                         M_ALL, H_DIM, V_DIM);
    }

    // 2) h_0 = tanh(xh_0) + bf16 split + barrier reset
    init_kernel<<<BH / (256 * 4), 256>>>(xh, hs);

    // 3) pad (ncu slot alignment)
    pad_kernel<<<1, 32>>>(1u);

    // 4) all 255 recurrence steps (warp-level k-split, one barrier/step)
    rnn_persistent_mma<<<NBLK, 512, PS_SMEM>>>(W_hh, xh, hs);

    // 5) outputs = hs @ W_dense + b_dense : [65536,1024] x [1024,512]
    {
        dim3 grid(V_DIM / 128, M_ALL / 128);
        sgemm_bias_kernel<<<grid, 256>>>(hs, W_dense, b_dense, out,
                                         M_ALL, V_DIM, H_DIM);
    }

    // 6) state = h_{T-1}
    if (out_size >= TBV + BH) {
        copy_kernel<<<BH / (256 * 4), 256>>>(hs + (size_t)(T_DIM - 1) * BH,
                                             out + TBV);
    }
}